// round 5
// baseline (speedup 1.0000x reference)
#include <cuda_runtime.h>
#include <cstdint>

using ull = unsigned long long;
#define NROW 1024
#define NDIM 256
#define ROWS 4          // rows per CTA (2 f32x2 pairs)
#define ICH  32         // i-lanes per CTA (covers i and i^128 -> 64 outputs)
#define JG   8          // j-interleave groups (one per warp)

__device__ __forceinline__ void fma2(ull& d, ull a, ull b) {
    asm("fma.rn.f32x2 %0, %1, %2, %0;" : "+l"(d) : "l"(a), "l"(b));
}
__device__ __forceinline__ ull mul2(ull a, ull b) {
    ull r; asm("mul.rn.f32x2 %0, %1, %2;" : "=l"(r) : "l"(a), "l"(b));
    return r;
}
// suffix-parity mask: bit p of Uof(j) = parity of bits of j strictly above p.
// XOR-linear: Uof(a^b) = Uof(a)^Uof(b).  Uof(128)=127, bit7 always 0.
__host__ __device__ constexpr unsigned Uof(unsigned j) {
    unsigned v = j >> 1; v ^= v >> 1; v ^= v >> 2; v ^= v >> 4;
    return v & 255u;
}

__global__ void __launch_bounds__(256)
clifford_kernel(const float* __restrict__ A, const float* __restrict__ B,
                float* __restrict__ out) {
    __shared__ union SmemU {
        struct { float4 As[NDIM]; float4 Bs[NDIM]; } t;   // 8KB tiles
        ull stage[12][JG][ICH];                            // 24KB staging
    } sm;

    const unsigned tid = threadIdx.x;
    const unsigned gb  = blockIdx.x >> 2;   // row-group 0..255
    const unsigned ic  = blockIdx.x & 3;    // i-chunk   0..3 (i in [0,128))
    const unsigned rowBase = gb * ROWS;
    const unsigned ibase   = ic * ICH;

    // ---- fill: thread tid stages component j = tid for 4 rows ----
    {
        const unsigned j = tid;
        const float sg = (__popc(j & Uof(j)) & 1) ? -1.0f : 1.0f;
        float av[4], bv[4];
        #pragma unroll
        for (int r = 0; r < 4; ++r) {
            av[r] = A[(size_t)(rowBase + r) * NDIM + j] * sg;
            bv[r] = B[(size_t)(rowBase + r) * NDIM + j];
        }
        sm.t.As[j] = make_float4(av[0], av[1], av[2], av[3]);  // pairs (r0,r1),(r2,r3)
        sm.t.Bs[j] = make_float4(bv[0], bv[1], bv[2], bv[3]);
    }
    __syncthreads();

    const unsigned il = tid & 31;
    const unsigned jg = tid >> 5;
    const unsigned i  = ibase + il;         // i < 128; second output is i^128

    // hoisted per-thread constants
    const unsigned xbase  = i ^ jg;
    const unsigned ph     = (unsigned)(__popc(i & Uof(jg)) & 1) << 31;
    const unsigned sgb1   = 0x3f800000u ^ ph;                          // for output i
    const unsigned sgb2   = sgb1 ^ ((unsigned)(__popc(i) & 1) << 31);  // for output i^128
    const unsigned g1     = jg & ~i;        // low part of (j & ~i), low7-safe
    const unsigned g2     = i & jg;         // low part of (i & j)
    const unsigned s0     = i & ~jg & 127u; // low part of (i & ~j)

    ull acc[12];                            // [prod*4 + ihalf*2 + pair]
    #pragma unroll
    for (int q = 0; q < 12; ++q) acc[q] = 0ull;

    const ulonglong2* __restrict__ Asp = reinterpret_cast<const ulonglong2*>(&sm.t.As[0]);
    const ulonglong2* __restrict__ Bsp = reinterpret_cast<const ulonglong2*>(&sm.t.Bs[0]);

    #pragma unroll
    for (unsigned m = 0; m < 32; ++m) {
        const unsigned jh = 8u * m;              // compile-time
        const unsigned jl = jh & 127u;           // compile-time
        const bool     h  = (jh & 128u) != 0u;   // compile-time
        const unsigned cU = Uof(jh);             // compile-time

        const unsigned j  = jh | jg;
        const unsigned x  = xbase ^ jh;

        const unsigned pc  = ((unsigned)__popc(i & cU) & 1u) << 31;
        const unsigned sg1 = sgb1 ^ pc;
        const unsigned sg2 = sgb2 ^ pc;
        const ull sg1_64 = ((ull)sg1 << 32) | sg1;
        const ull sg2_64 = ((ull)sg2 << 32) | sg2;

        const bool W = (((jl & ~i) | g1) == 0u);     // j subset of i (low 7)
        const bool D = (((i & jl) | g2) == 0u);      // disjoint (low 7)
        const bool S = ((s0 & (~jl & 127u)) == 0u);  // i subset of j (low 7)

        const bool pw1 = (!h) && W;      // wedge for output i   (needs j7==0)
        const bool pw2 = W;              // wedge for output i^128 at j^128
        const bool pi1 = D | S;          // inner for output i
        const bool pi2 = h ? D : S;      // inner for output i^128 at j^128

        const ulonglong2 a1 = Asp[j];          // broadcast
        const ulonglong2 a2 = Asp[j ^ 128u];   // broadcast
        const ulonglong2 b  = Bsp[x];          // conflict-free gather, shared by both outputs

        // output i (terms j)
        ull t;
        t = mul2(a1.x, b.x);
        fma2(acc[0], t, sg1_64); if (pw1) fma2(acc[4], t, sg1_64); if (pi1) fma2(acc[8],  t, sg1_64);
        t = mul2(a1.y, b.y);
        fma2(acc[1], t, sg1_64); if (pw1) fma2(acc[5], t, sg1_64); if (pi1) fma2(acc[9],  t, sg1_64);
        // output i^128 (terms j^128), reusing b
        t = mul2(a2.x, b.x);
        fma2(acc[2], t, sg2_64); if (pw2) fma2(acc[6], t, sg2_64); if (pi2) fma2(acc[10], t, sg2_64);
        t = mul2(a2.y, b.y);
        fma2(acc[3], t, sg2_64); if (pw2) fma2(acc[7], t, sg2_64); if (pi2) fma2(acc[11], t, sg2_64);
    }

    // ---- deterministic cross-warp reduction over the 8 j-groups ----
    __syncthreads();                 // tiles fully consumed before overwrite
    #pragma unroll
    for (int q = 0; q < 12; ++q)
        sm.stage[q][jg][il] = acc[q];
    __syncthreads();

    {
        const unsigned qh0 = (tid >> 5) * 3;        // 3 outputs per thread
        #pragma unroll
        for (int k = 0; k < 3; ++k) {
            const unsigned qh   = qh0 + k;          // 0..23 = prod*8 + ihalf*4 + row
            const unsigned prod = qh >> 3;
            const unsigned rem  = qh & 7;
            const unsigned ih   = rem >> 2;         // 0: i, 1: i^128
            const unsigned r    = rem & 3;          // row 0..3
            const unsigned q    = prod * 4 + ih * 2 + (r >> 1);
            const unsigned hf   = r & 1;
            const float* sp = reinterpret_cast<const float*>(&sm.stage[q][0][0]);
            float s = 0.0f;
            #pragma unroll
            for (int w = 0; w < 8; ++w)
                s += sp[(w * ICH + il) * 2 + hf];
            out[(size_t)prod * (NROW * NDIM)
                + (size_t)(rowBase + r) * NDIM
                + ih * 128u + ibase + il] = s;
        }
    }
}

extern "C" void kernel_launch(void* const* d_in, const int* in_sizes, int n_in,
                              void* d_out, int out_size) {
    const float* A = (const float*)d_in[0];
    const float* B = (const float*)d_in[1];
    float* out = (float*)d_out;
    // 1024 rows / 4 rows-per-CTA = 256 row-groups; x 4 i-chunks = 1024 CTAs
    clifford_kernel<<<1024, 256>>>(A, B, out);
}